// round 2
// baseline (speedup 1.0000x reference)
#include <cuda_runtime.h>

#define NMAX 1000000
#define CC 16
#define KS 9

// Scratch (allocation-free rule: __device__ globals)
__device__ float g_z1[(size_t)NMAX * CC];
__device__ float g_z2[(size_t)NMAX * CC];
__device__ float g_stats[64];  // [0:16) sum1, [16:32) sumsq1, [32:48) sum2, [48:64) sumsq2

typedef unsigned long long ull;

// ---- packed f32x2 helpers (FFMA2 path, sm_100+) ----
__device__ __forceinline__ ull pack2(float lo, float hi) {
    ull d;
    asm("mov.b64 %0, {%1, %2};" : "=l"(d) : "r"(__float_as_uint(lo)), "r"(__float_as_uint(hi)));
    return d;
}
__device__ __forceinline__ ull bcast2(float x) {
    ull d;
    asm("mov.b64 %0, {%1, %1};" : "=l"(d) : "r"(__float_as_uint(x)));
    return d;
}
__device__ __forceinline__ void fma2(ull& d, ull a, ull b) {
    asm("fma.rn.f32x2 %0, %1, %2, %0;" : "+l"(d) : "l"(a), "l"(b));
}
__device__ __forceinline__ float2 unpack2(ull v) {
    unsigned lo, hi;
    asm("mov.b64 {%0, %1}, %2;" : "=r"(lo), "=r"(hi) : "l"(v));
    return make_float2(__uint_as_float(lo), __uint_as_float(hi));
}

__device__ __forceinline__ float leaky(float x) {
    // slope 0.2 < 1 so leaky(x) == max(x, 0.2x)
    return fmaxf(x, 0.2f * x);
}

// ---------------------------------------------------------------------------
// K0: zero the stats accumulators (graph replays must reset them)
// ---------------------------------------------------------------------------
__global__ void k0_init() {
    if (threadIdx.x < 64) g_stats[threadIdx.x] = 0.0f;
}

// ---------------------------------------------------------------------------
// Shared conv core: per-thread conv of one point given a row-provider.
// ws layout: ws[(j*16 + c)*16 + o]  (o contiguous, paired for f32x2)
// ---------------------------------------------------------------------------

// K1: gather(data) -> conv1 + bias -> z1, accumulate BN1 stats
__global__ __launch_bounds__(256) void k1_conv1(
    const float* __restrict__ data, const int* __restrict__ ind,
    const float* __restrict__ w1, const float* __restrict__ b1, int N)
{
    __shared__ __align__(16) float ws[KS * CC * CC];
    __shared__ float bsh[CC];
    for (int i = threadIdx.x; i < KS * CC * CC; i += 256) {
        int j = i >> 8, c = (i >> 4) & 15, o = i & 15;
        ws[i] = w1[(c * CC + o) * KS + j];
    }
    if (threadIdx.x < CC) bsh[threadIdx.x] = b1[threadIdx.x];
    __syncthreads();

    int n = blockIdx.x * 256 + threadIdx.x;
    float z[CC];
#pragma unroll
    for (int o = 0; o < CC; ++o) z[o] = 0.0f;

    if (n < N) {
        ull acc[8];
#pragma unroll
        for (int p = 0; p < 8; ++p) acc[p] = pack2(bsh[2 * p], bsh[2 * p + 1]);

        int idx[KS];
#pragma unroll
        for (int j = 0; j < KS; ++j) idx[j] = ind[n * KS + j];

#pragma unroll
        for (int j = 0; j < KS; ++j) {
            const float4* dr = reinterpret_cast<const float4*>(data) + (size_t)idx[j] * 4;
            float4 r0 = dr[0], r1 = dr[1], r2 = dr[2], r3 = dr[3];
            float rc[16] = {r0.x, r0.y, r0.z, r0.w, r1.x, r1.y, r1.z, r1.w,
                            r2.x, r2.y, r2.z, r2.w, r3.x, r3.y, r3.z, r3.w};
#pragma unroll
            for (int c = 0; c < CC; ++c) {
                ull rp = bcast2(rc[c]);
                const ulonglong2* wv =
                    reinterpret_cast<const ulonglong2*>(&ws[(j * CC + c) * CC]);
                ulonglong2 wA = wv[0], wB = wv[1], wC = wv[2], wD = wv[3];
                fma2(acc[0], rp, wA.x); fma2(acc[1], rp, wA.y);
                fma2(acc[2], rp, wB.x); fma2(acc[3], rp, wB.y);
                fma2(acc[4], rp, wC.x); fma2(acc[5], rp, wC.y);
                fma2(acc[6], rp, wD.x); fma2(acc[7], rp, wD.y);
            }
        }
#pragma unroll
        for (int p = 0; p < 8; ++p) {
            float2 u = unpack2(acc[p]);
            z[2 * p] = u.x; z[2 * p + 1] = u.y;
        }
        float4* zo = reinterpret_cast<float4*>(g_z1 + (size_t)n * CC);
        zo[0] = make_float4(z[0], z[1], z[2], z[3]);
        zo[1] = make_float4(z[4], z[5], z[6], z[7]);
        zo[2] = make_float4(z[8], z[9], z[10], z[11]);
        zo[3] = make_float4(z[12], z[13], z[14], z[15]);
    }

    // BN1 stats: warp-reduce then one atomic per warp per channel
    int lane = threadIdx.x & 31;
#pragma unroll
    for (int o = 0; o < CC; ++o) {
        float s = z[o], q = z[o] * z[o];
#pragma unroll
        for (int off = 16; off; off >>= 1) {
            s += __shfl_xor_sync(0xffffffffu, s, off);
            q += __shfl_xor_sync(0xffffffffu, q, off);
        }
        if (lane == 0) {
            atomicAdd(&g_stats[o], s);
            atomicAdd(&g_stats[16 + o], q);
        }
    }
}

// K2: gather(leaky(bn1(z1))) -> conv2 -> z2, accumulate BN2 stats
__global__ __launch_bounds__(256) void k2_conv2(
    const int* __restrict__ ind, const float* __restrict__ w2,
    const float* __restrict__ gamma1, const float* __restrict__ beta1,
    int N, float invN)
{
    __shared__ __align__(16) float ws[KS * CC * CC];
    __shared__ float a1s[CC], c1s[CC];
    for (int i = threadIdx.x; i < KS * CC * CC; i += 256) {
        int j = i >> 8, c = (i >> 4) & 15, o = i & 15;
        ws[i] = w2[(c * CC + o) * KS + j];
    }
    if (threadIdx.x < CC) {
        int o = threadIdx.x;
        float mean = g_stats[o] * invN;
        float var  = g_stats[16 + o] * invN - mean * mean;
        float a = gamma1[o] * rsqrtf(var + 1e-5f);
        a1s[o] = a;
        c1s[o] = fmaf(-mean, a, beta1[o]);
    }
    __syncthreads();

    int n = blockIdx.x * 256 + threadIdx.x;
    float z[CC];
#pragma unroll
    for (int o = 0; o < CC; ++o) z[o] = 0.0f;

    if (n < N) {
        ull acc[8];
#pragma unroll
        for (int p = 0; p < 8; ++p) acc[p] = 0ull;

        int idx[KS];
#pragma unroll
        for (int j = 0; j < KS; ++j) idx[j] = ind[n * KS + j];

#pragma unroll
        for (int j = 0; j < KS; ++j) {
            const float4* dr = reinterpret_cast<const float4*>(g_z1) + (size_t)idx[j] * 4;
            float4 r0 = dr[0], r1 = dr[1], r2 = dr[2], r3 = dr[3];
            float rc[16] = {r0.x, r0.y, r0.z, r0.w, r1.x, r1.y, r1.z, r1.w,
                            r2.x, r2.y, r2.z, r2.w, r3.x, r3.y, r3.z, r3.w};
            // BN1 + LeakyReLU applied on the gathered row
#pragma unroll
            for (int c = 0; c < CC; ++c) {
                float v = fmaf(a1s[c], rc[c], c1s[c]);
                rc[c] = leaky(v);
            }
#pragma unroll
            for (int c = 0; c < CC; ++c) {
                ull rp = bcast2(rc[c]);
                const ulonglong2* wv =
                    reinterpret_cast<const ulonglong2*>(&ws[(j * CC + c) * CC]);
                ulonglong2 wA = wv[0], wB = wv[1], wC = wv[2], wD = wv[3];
                fma2(acc[0], rp, wA.x); fma2(acc[1], rp, wA.y);
                fma2(acc[2], rp, wB.x); fma2(acc[3], rp, wB.y);
                fma2(acc[4], rp, wC.x); fma2(acc[5], rp, wC.y);
                fma2(acc[6], rp, wD.x); fma2(acc[7], rp, wD.y);
            }
        }
#pragma unroll
        for (int p = 0; p < 8; ++p) {
            float2 u = unpack2(acc[p]);
            z[2 * p] = u.x; z[2 * p + 1] = u.y;
        }
        float4* zo = reinterpret_cast<float4*>(g_z2 + (size_t)n * CC);
        zo[0] = make_float4(z[0], z[1], z[2], z[3]);
        zo[1] = make_float4(z[4], z[5], z[6], z[7]);
        zo[2] = make_float4(z[8], z[9], z[10], z[11]);
        zo[3] = make_float4(z[12], z[13], z[14], z[15]);
    }

    int lane = threadIdx.x & 31;
#pragma unroll
    for (int o = 0; o < CC; ++o) {
        float s = z[o], q = z[o] * z[o];
#pragma unroll
        for (int off = 16; off; off >>= 1) {
            s += __shfl_xor_sync(0xffffffffu, s, off);
            q += __shfl_xor_sync(0xffffffffu, q, off);
        }
        if (lane == 0) {
            atomicAdd(&g_stats[32 + o], s);
            atomicAdd(&g_stats[48 + o], q);
        }
    }
}

// K3: out = leaky(bn2(z2) + data), vectorized float4
__global__ __launch_bounds__(256) void k3_epilogue(
    const float* __restrict__ data, const float* __restrict__ gamma2,
    const float* __restrict__ beta2, float* __restrict__ out,
    int N, float invN)
{
    __shared__ float a2s[CC], c2s[CC];
    if (threadIdx.x < CC) {
        int o = threadIdx.x;
        float mean = g_stats[32 + o] * invN;
        float var  = g_stats[48 + o] * invN - mean * mean;
        float a = gamma2[o] * rsqrtf(var + 1e-5f);
        a2s[o] = a;
        c2s[o] = fmaf(-mean, a, beta2[o]);
    }
    __syncthreads();

    int total4 = N * 4;  // N*16 floats / 4
    const float4* z4 = reinterpret_cast<const float4*>(g_z2);
    const float4* d4 = reinterpret_cast<const float4*>(data);
    float4* o4 = reinterpret_cast<float4*>(out);
    for (int i = blockIdx.x * blockDim.x + threadIdx.x; i < total4;
         i += gridDim.x * blockDim.x) {
        float4 zv = z4[i];
        float4 dv = d4[i];
        int cb = (i & 3) * 4;
        float4 r;
        r.x = leaky(fmaf(a2s[cb + 0], zv.x, c2s[cb + 0]) + dv.x);
        r.y = leaky(fmaf(a2s[cb + 1], zv.y, c2s[cb + 1]) + dv.y);
        r.z = leaky(fmaf(a2s[cb + 2], zv.z, c2s[cb + 2]) + dv.z);
        r.w = leaky(fmaf(a2s[cb + 3], zv.w, c2s[cb + 3]) + dv.w);
        o4[i] = r;
    }
}

extern "C" void kernel_launch(void* const* d_in, const int* in_sizes, int n_in,
                              void* d_out, int out_size)
{
    const float* data   = (const float*)d_in[0];
    const int*   ind    = (const int*)d_in[1];
    const float* w1     = (const float*)d_in[2];
    const float* b1     = (const float*)d_in[3];
    const float* gamma1 = (const float*)d_in[4];
    const float* beta1  = (const float*)d_in[5];
    const float* w2     = (const float*)d_in[6];
    const float* gamma2 = (const float*)d_in[7];
    const float* beta2  = (const float*)d_in[8];

    int N = in_sizes[0] / CC;
    if (N > NMAX) N = NMAX;
    float invN = 1.0f / (float)N;
    int blocks = (N + 255) / 256;

    k0_init<<<1, 64>>>();
    k1_conv1<<<blocks, 256>>>(data, ind, w1, b1, N);
    k2_conv2<<<blocks, 256>>>(ind, w2, gamma1, beta1, N, invN);
    k3_epilogue<<<1024, 256>>>(data, gamma2, beta2, (float*)d_out, N, invN);
}